// round 1
// baseline (speedup 1.0000x reference)
#include <cuda_runtime.h>

#define NN 12288
#define NE 393216
#define EPSF 1e-8f
#define CAP 224

// ---- scratch (static device globals; no allocation in kernel_launch) ----
__device__ float g_xn[NN * 64];            // x / ||x||  (for edge cosines)
__device__ float g_sf[NN * 64];            // normalize(x @ W_self^T)
__device__ float g_an[NN * 64];            // normalize(x @ W_neigh^T)
__device__ float g_w[NE];                  // per-edge clip weights
__device__ unsigned int g_deg[NN];
__device__ unsigned int g_off[NN + 1];
__device__ unsigned int g_cur[NN];
__device__ unsigned long long g_ent[2 * NE];  // packed (key<<14 | j)

__device__ __forceinline__ float wred(float v) {
#pragma unroll
    for (int o = 16; o; o >>= 1) v += __shfl_xor_sync(0xffffffffu, v, o);
    return v;
}

__global__ void k_zero() {
    int t = blockIdx.x * blockDim.x + threadIdx.x;
    if (t < NN) { g_deg[t] = 0u; g_cur[t] = 0u; }
}

// One warp per node: both 64x64 GEMV projections + normalizations + x-hat.
__global__ __launch_bounds__(256) void k_transform(const float* __restrict__ x,
                                                   const float* __restrict__ Ws,
                                                   const float* __restrict__ Wn) {
    __shared__ float sWs[64 * 64];  // transposed [k][d] -> conflict-free
    __shared__ float sWn[64 * 64];
    for (int t = threadIdx.x; t < 4096; t += 256) {
        int d = t >> 6, k = t & 63;
        sWs[k * 64 + d] = Ws[t];
        sWn[k * 64 + d] = Wn[t];
    }
    __syncthreads();
    int warp = threadIdx.x >> 5, lane = threadIdx.x & 31;
    int i = blockIdx.x * 8 + warp;
    if (i >= NN) return;
    float x0 = x[i * 64 + lane];
    float x1 = x[i * 64 + 32 + lane];
    float s0 = 0.f, s1 = 0.f, a0 = 0.f, a1 = 0.f;
#pragma unroll
    for (int k = 0; k < 32; k++) {
        float xk = __shfl_sync(0xffffffffu, x0, k);
        s0 += xk * sWs[k * 64 + lane];      s1 += xk * sWs[k * 64 + 32 + lane];
        a0 += xk * sWn[k * 64 + lane];      a1 += xk * sWn[k * 64 + 32 + lane];
    }
#pragma unroll
    for (int k = 0; k < 32; k++) {
        float xk = __shfl_sync(0xffffffffu, x1, k);
        s0 += xk * sWs[(k + 32) * 64 + lane];      s1 += xk * sWs[(k + 32) * 64 + 32 + lane];
        a0 += xk * sWn[(k + 32) * 64 + lane];      a1 += xk * sWn[(k + 32) * 64 + 32 + lane];
    }
    float nx = wred(x0 * x0 + x1 * x1);
    float ns = wred(s0 * s0 + s1 * s1);
    float na = wred(a0 * a0 + a1 * a1);
    float rx = 1.f / sqrtf(nx);              // cos denom (+eps on product) negligible
    float rs = 1.f / (sqrtf(ns) + EPSF);
    float ra = 1.f / (sqrtf(na) + EPSF);
    g_xn[i * 64 + lane] = x0 * rx;  g_xn[i * 64 + 32 + lane] = x1 * rx;
    g_sf[i * 64 + lane] = s0 * rs;  g_sf[i * 64 + 32 + lane] = s1 * rs;
    g_an[i * 64 + lane] = a0 * ra;  g_an[i * 64 + 32 + lane] = a1 * ra;
}

// One warp per edge: cosine weight + degree counts (both directions).
__global__ __launch_bounds__(256) void k_edge(const int* __restrict__ ei) {
    int warp = threadIdx.x >> 5, lane = threadIdx.x & 31;
    int k = blockIdx.x * 8 + warp;
    if (k >= NE) return;
    int r = ei[k], c = ei[NE + k];
    float d = g_xn[r * 64 + lane] * g_xn[c * 64 + lane]
            + g_xn[r * 64 + 32 + lane] * g_xn[c * 64 + 32 + lane];
    d = wred(d);
    if (lane == 0) {
        float w = fminf(fmaxf((d + 1.f) * 0.5f, 0.1f), 0.9f);
        g_w[k] = w;
        atomicAdd(&g_deg[r], 1u);
        atomicAdd(&g_deg[c], 1u);
    }
}

// Single-block exclusive scan of g_deg -> g_off (12288 = 1024 x 12).
__global__ __launch_bounds__(1024) void k_scan() {
    __shared__ unsigned int ts[1024];
    int t = threadIdx.x;
    unsigned int v[12];
    unsigned int s = 0;
    int base = t * 12;
#pragma unroll
    for (int j = 0; j < 12; j++) { v[j] = g_deg[base + j]; s += v[j]; }
    ts[t] = s;
    __syncthreads();
    for (int o = 1; o < 1024; o <<= 1) {
        unsigned int add = (t >= o) ? ts[t - o] : 0u;
        __syncthreads();
        ts[t] += add;
        __syncthreads();
    }
    unsigned int run = (t == 0) ? 0u : ts[t - 1];
#pragma unroll
    for (int j = 0; j < 12; j++) { g_off[base + j] = run; run += v[j]; }
    if (t == 1023) g_off[NN] = run;
}

// Scatter both directed incidences with keys encoding .set() write order:
// pass-1 (row,col) key=k ; pass-2 (col,row) key=E+k (always wins over pass-1).
__global__ __launch_bounds__(256) void k_scatter(const int* __restrict__ ei) {
    int k = blockIdx.x * blockDim.x + threadIdx.x;
    if (k >= NE) return;
    int r = ei[k], c = ei[NE + k];
    unsigned int p = atomicAdd(&g_cur[r], 1u);
    g_ent[g_off[r] + p] = ((unsigned long long)(unsigned)k << 14) | (unsigned)c;
    unsigned int q = atomicAdd(&g_cur[c], 1u);
    g_ent[g_off[c] + q] = ((unsigned long long)(unsigned)(k + NE) << 14) | (unsigned)r;
}

// One warp per node: dedup (max-key wins per neighbor j), weighted gather of
// an-features, implicit diagonal, then the full normalize/blend epilogue.
__global__ __launch_bounds__(256) void k_agg(const float* __restrict__ bias,
                                             float* __restrict__ out) {
    __shared__ unsigned long long sbuf[8][CAP];
    int warp = threadIdx.x >> 5, lane = threadIdx.x & 31;
    float b0 = bias[lane], b1 = bias[lane + 32];
    float nb = sqrtf(wred(b0 * b0 + b1 * b1) + 1.0f);  // ||[bias,1]||
    float bp0 = b0 / nb, bp1 = b1 / nb;
    int i = blockIdx.x * 8 + warp;
    if (i >= NN) return;
    unsigned int o0 = g_off[i], o1 = g_off[i + 1];
    int deg = (int)(o1 - o0);
    const unsigned long long* lst;
    if (deg <= CAP) {
        for (int e = lane; e < deg; e += 32) sbuf[warp][e] = g_ent[o0 + e];
        __syncwarp();
        lst = sbuf[warp];
    } else {
        lst = &g_ent[o0];  // safety fallback; deg ~ Poisson(64), never hit
    }
    float acc0 = 0.f, acc1 = 0.f;
    int hasSelf = 0;
    for (int basee = 0; basee < deg; basee += 32) {
        int e = basee + lane;
        bool act = e < deg;
        unsigned long long pe = act ? lst[e] : 0ULL;
        unsigned int j = (unsigned int)(pe & 0x3FFFULL);
        bool surv = act;
        if (act) {
            for (int t = 0; t < deg; t++) {
                unsigned long long pt = lst[t];
                if ((unsigned int)(pt & 0x3FFFULL) == j && pt > pe) { surv = false; break; }
            }
        }
        unsigned int mask = __ballot_sync(0xffffffffu, surv);
        while (mask) {
            int src = __ffs(mask) - 1;
            mask &= mask - 1;
            unsigned long long ps = __shfl_sync(0xffffffffu, pe, src);
            unsigned int js = (unsigned int)(ps & 0x3FFFULL);
            unsigned int key = (unsigned int)(ps >> 14);
            float wv = g_w[key >= NE ? key - NE : key];
            if (js == (unsigned int)i) hasSelf = 1;
            acc0 += wv * g_an[js * 64 + lane];
            acc1 += wv * g_an[js * 64 + 32 + lane];
        }
    }
    if (!hasSelf) {  // diagonal weight 1 survives only if never overwritten
        acc0 += g_an[i * 64 + lane];
        acc1 += g_an[i * 64 + 32 + lane];
    }
    // epilogue: nf = normalize(acc); u = normalize(0.5 s + 0.5 nf);
    // m = normalize(0.9 u + 0.1 bp); final = normalize(m)
    float na = wred(acc0 * acc0 + acc1 * acc1);
    float rn = 1.f / (sqrtf(na) + EPSF);
    float n0 = acc0 * rn, n1 = acc1 * rn;
    float s0 = g_sf[i * 64 + lane], s1 = g_sf[i * 64 + 32 + lane];
    float u0 = 0.5f * (s0 + n0), u1 = 0.5f * (s1 + n1);
    float nu = wred(u0 * u0 + u1 * u1);
    float ru = 1.f / (sqrtf(nu) + EPSF);
    u0 *= ru; u1 *= ru;
    float m0 = 0.9f * u0 + 0.1f * bp0, m1 = 0.9f * u1 + 0.1f * bp1;
    float nm = wred(m0 * m0 + m1 * m1);
    float rm = 1.f / (sqrtf(nm) + EPSF);
    m0 *= rm; m1 *= rm;
    float nrm2 = sqrtf(nm) * rm;       // norm of (m0,m1) after scaling (~1)
    float rf = 1.f / (nrm2 + EPSF);
    out[i * 64 + lane]      = m0 * rf;
    out[i * 64 + 32 + lane] = m1 * rf;
}

extern "C" void kernel_launch(void* const* d_in, const int* in_sizes, int n_in,
                              void* d_out, int out_size) {
    const float* x  = (const float*)d_in[0];
    const int*   ei = (const int*)d_in[1];
    const float* Ws = (const float*)d_in[2];
    const float* Wn = (const float*)d_in[3];
    const float* b  = (const float*)d_in[4];
    float* out = (float*)d_out;

    k_zero<<<(NN + 255) / 256, 256>>>();
    k_transform<<<NN / 8, 256>>>(x, Ws, Wn);
    k_edge<<<NE / 8, 256>>>(ei);
    k_scan<<<1, 1024>>>();
    k_scatter<<<NE / 256, 256>>>(ei);
    k_agg<<<NN / 8, 256>>>(b, out);
}

// round 2
// speedup vs baseline: 1.7128x; 1.7128x over previous
#include <cuda_runtime.h>

#define NN 12288
#define NE 393216
#define EPSF 1e-8f
#define CAPN 192          // fixed bucket capacity per node (deg ~ Poisson(64))

// ---- scratch (static device globals; no allocation in kernel_launch) ----
__device__ float g_xn[NN * 64];                 // x / ||x||  (for edge cosines)
__device__ float g_sf[NN * 64];                 // normalize(x @ W_self^T)
__device__ float g_an[NN * 64];                 // normalize(x @ W_neigh^T)
__device__ unsigned int g_cur[NN];              // per-node fill counters
__device__ unsigned long long g_ent[NN * CAPN]; // packed (key20 | w30 | j14)

__device__ __forceinline__ float wred(float v) {
#pragma unroll
    for (int o = 16; o; o >>= 1) v += __shfl_xor_sync(0xffffffffu, v, o);
    return v;
}

// ---------------------------------------------------------------------------
// 4 nodes per warp: both 64x64 GEMV projections + normalizations + x-hat.
// Also zeroes g_cur (ordering vs k_edge guaranteed by stream order).
// ---------------------------------------------------------------------------
__global__ __launch_bounds__(256) void k_transform(const float* __restrict__ x,
                                                   const float* __restrict__ Ws,
                                                   const float* __restrict__ Wn) {
    __shared__ float sWs[64 * 64];  // transposed: sW[k*64+d]
    __shared__ float sWn[64 * 64];
    for (int t = threadIdx.x; t < 4096; t += 256) {
        int d = t >> 6, k = t & 63;
        sWs[k * 64 + d] = Ws[t];
        sWn[k * 64 + d] = Wn[t];
    }
    __syncthreads();
    int warp = threadIdx.x >> 5, lane = threadIdx.x & 31;
    int i0 = blockIdx.x * 32 + warp * 4;
    if (lane < 4) g_cur[i0 + lane] = 0u;

    float xa0[4], xa1[4];
#pragma unroll
    for (int n = 0; n < 4; n++) {
        xa0[n] = x[(i0 + n) * 64 + lane];
        xa1[n] = x[(i0 + n) * 64 + 32 + lane];
    }
    float s0[4] = {0, 0, 0, 0}, s1[4] = {0, 0, 0, 0};
    float a0[4] = {0, 0, 0, 0}, a1[4] = {0, 0, 0, 0};
#pragma unroll
    for (int k = 0; k < 32; k++) {
        float ws0 = sWs[k * 64 + lane], ws1 = sWs[k * 64 + 32 + lane];
        float wn0 = sWn[k * 64 + lane], wn1 = sWn[k * 64 + 32 + lane];
#pragma unroll
        for (int n = 0; n < 4; n++) {
            float xk = __shfl_sync(0xffffffffu, xa0[n], k);
            s0[n] += xk * ws0; s1[n] += xk * ws1;
            a0[n] += xk * wn0; a1[n] += xk * wn1;
        }
    }
#pragma unroll
    for (int k = 0; k < 32; k++) {
        float ws0 = sWs[(k + 32) * 64 + lane], ws1 = sWs[(k + 32) * 64 + 32 + lane];
        float wn0 = sWn[(k + 32) * 64 + lane], wn1 = sWn[(k + 32) * 64 + 32 + lane];
#pragma unroll
        for (int n = 0; n < 4; n++) {
            float xk = __shfl_sync(0xffffffffu, xa1[n], k);
            s0[n] += xk * ws0; s1[n] += xk * ws1;
            a0[n] += xk * wn0; a1[n] += xk * wn1;
        }
    }
#pragma unroll
    for (int n = 0; n < 4; n++) {
        int i = i0 + n;
        float nx = wred(xa0[n] * xa0[n] + xa1[n] * xa1[n]);
        float ns = wred(s0[n] * s0[n] + s1[n] * s1[n]);
        float na = wred(a0[n] * a0[n] + a1[n] * a1[n]);
        float rx = 1.f / sqrtf(nx);
        float rs = 1.f / (sqrtf(ns) + EPSF);
        float ra = 1.f / (sqrtf(na) + EPSF);
        g_xn[i * 64 + lane] = xa0[n] * rx;  g_xn[i * 64 + 32 + lane] = xa1[n] * rx;
        g_sf[i * 64 + lane] = s0[n] * rs;   g_sf[i * 64 + 32 + lane] = s1[n] * rs;
        g_an[i * 64 + lane] = a0[n] * ra;   g_an[i * 64 + 32 + lane] = a1[n] * ra;
    }
}

// ---------------------------------------------------------------------------
// One warp per edge: cosine weight, then scatter BOTH directed incidences
// into fixed-capacity buckets. key = k (pass-1 write at (r,c)) or k+NE
// (pass-2 write at (c,r)); max key == last .set() writer.
// ---------------------------------------------------------------------------
__global__ __launch_bounds__(256) void k_edge(const int* __restrict__ ei) {
    int warp = threadIdx.x >> 5, lane = threadIdx.x & 31;
    int k = blockIdx.x * 8 + warp;
    if (k >= NE) return;
    int r = ei[k], c = ei[NE + k];
    float d = g_xn[r * 64 + lane] * g_xn[c * 64 + lane]
            + g_xn[r * 64 + 32 + lane] * g_xn[c * 64 + 32 + lane];
    d = wred(d);
    if (lane == 0) {
        float w = fminf(fmaxf((d + 1.f) * 0.5f, 0.1f), 0.9f);
        unsigned long long w30 = (unsigned long long)(__float_as_uint(w) >> 2);
        unsigned long long e1 = ((unsigned long long)(unsigned)k << 44) | (w30 << 14) | (unsigned)c;
        unsigned long long e2 = ((unsigned long long)(unsigned)(k + NE) << 44) | (w30 << 14) | (unsigned)r;
        unsigned int p = atomicAdd(&g_cur[r], 1u);
        if (p < CAPN) g_ent[r * CAPN + p] = e1;
        unsigned int q = atomicAdd(&g_cur[c], 1u);
        if (q < CAPN) g_ent[c * CAPN + q] = e2;
    }
}

// ---------------------------------------------------------------------------
// One warp per node: hash-table dedup (max packed value = max key wins),
// compact to (j, w) list, then counted unroll-4 gather + epilogue.
// ---------------------------------------------------------------------------
__global__ __launch_bounds__(256) void k_agg(const float* __restrict__ bias,
                                             float* __restrict__ out) {
    __shared__ unsigned long long tab[8][256];
    __shared__ int   sj[8][CAPN];
    __shared__ float sw[8][CAPN];
    int warp = threadIdx.x >> 5, lane = threadIdx.x & 31;

    float b0 = bias[lane], b1 = bias[lane + 32];
    float nb = sqrtf(wred(b0 * b0 + b1 * b1) + 1.0f);   // ||[bias,1]||
    float bp0 = b0 / nb, bp1 = b1 / nb;

    int i = blockIdx.x * 8 + warp;

    // zero this warp's hash table
#pragma unroll
    for (int t = lane; t < 256; t += 32) tab[warp][t] = 0ULL;
    __syncwarp();

    int deg = (int)min(g_cur[i], (unsigned)CAPN);
    // insert all entries (same-j resolves to max key via atomicMax)
    for (int base = 0; base < deg; base += 32) {
        int e = base + lane;
        if (e < deg) {
            unsigned long long pe = g_ent[i * CAPN + e];
            unsigned int j = (unsigned int)(pe & 0x3FFFULL);
            unsigned int h = (j * 0x9E3779B1u) >> 24;
            for (;;) {
                unsigned long long cur = tab[warp][h];
                if (cur == 0ULL) {
                    unsigned long long old = atomicCAS(&tab[warp][h], 0ULL, pe);
                    if (old == 0ULL) break;
                    cur = old;
                }
                if ((unsigned int)(cur & 0x3FFFULL) == j) { atomicMax(&tab[warp][h], pe); break; }
                h = (h + 1) & 255;
            }
        }
    }
    __syncwarp();

    // compact occupied slots to a dense (j, w) list
    int cnt = 0, selfFlag = 0;
#pragma unroll
    for (int base = 0; base < 256; base += 32) {
        unsigned long long pe = tab[warp][base + lane];
        bool occ = pe != 0ULL;
        unsigned int j = (unsigned int)(pe & 0x3FFFULL);
        if (occ && j == (unsigned)i) selfFlag = 1;
        unsigned int mask = __ballot_sync(0xffffffffu, occ);
        int pos = cnt + __popc(mask & ((1u << lane) - 1u));
        if (occ) {
            sj[warp][pos] = (int)j;
            sw[warp][pos] = __uint_as_float(((unsigned int)(pe >> 14) & 0x3FFFFFFFu) << 2);
        }
        cnt += __popc(mask);
    }
    int hasSelf = (__ballot_sync(0xffffffffu, selfFlag) != 0u);
    __syncwarp();

    // counted gather: independent iterations -> MLP
    float acc0 = 0.f, acc1 = 0.f;
#pragma unroll 4
    for (int e = 0; e < cnt; e++) {
        int js = sj[warp][e];
        float wv = sw[warp][e];
        acc0 += wv * g_an[js * 64 + lane];
        acc1 += wv * g_an[js * 64 + 32 + lane];
    }
    if (!hasSelf) {  // eye diagonal survives only when no edge overwrote it
        acc0 += g_an[i * 64 + lane];
        acc1 += g_an[i * 64 + 32 + lane];
    }

    // epilogue: nf = normalize(acc); u = normalize(0.5 s + 0.5 nf);
    // m = normalize(0.9 u + 0.1 bp); final = m / (||m|| + eps)
    float na = wred(acc0 * acc0 + acc1 * acc1);
    float rn = 1.f / (sqrtf(na) + EPSF);
    float n0 = acc0 * rn, n1 = acc1 * rn;
    float s0 = g_sf[i * 64 + lane], s1 = g_sf[i * 64 + 32 + lane];
    float u0 = 0.5f * (s0 + n0), u1 = 0.5f * (s1 + n1);
    float nu = wred(u0 * u0 + u1 * u1);
    float ru = 1.f / (sqrtf(nu) + EPSF);
    u0 *= ru; u1 *= ru;
    float m0 = 0.9f * u0 + 0.1f * bp0, m1 = 0.9f * u1 + 0.1f * bp1;
    float nm = wred(m0 * m0 + m1 * m1);
    float rm = 1.f / (sqrtf(nm) + EPSF);
    m0 *= rm; m1 *= rm;
    float nrm2 = sqrtf(nm) * rm;   // ~1
    float rf = 1.f / (nrm2 + EPSF);
    out[i * 64 + lane]      = m0 * rf;
    out[i * 64 + 32 + lane] = m1 * rf;
}

extern "C" void kernel_launch(void* const* d_in, const int* in_sizes, int n_in,
                              void* d_out, int out_size) {
    const float* x  = (const float*)d_in[0];
    const int*   ei = (const int*)d_in[1];
    const float* Ws = (const float*)d_in[2];
    const float* Wn = (const float*)d_in[3];
    const float* b  = (const float*)d_in[4];
    float* out = (float*)d_out;

    k_transform<<<NN / 32, 256>>>(x, Ws, Wn);
    k_edge<<<NE / 8, 256>>>(ei);
    k_agg<<<NN / 8, 256>>>(b, out);
}

// round 3
// speedup vs baseline: 1.8071x; 1.0550x over previous
#include <cuda_runtime.h>
#include <cuda_fp16.h>

#define NN 12288
#define NE 393216
#define EPSF 1e-8f
#define CAPN 192          // fixed bucket capacity per node (deg ~ Poisson(64))

// ---- scratch (static device globals; no allocation in kernel_launch) ----
__device__ __half g_xnh[NN * 64];               // fp16 x/||x|| (edge cosines)
__device__ __half g_anh[NN * 64];               // fp16 normalize(x @ Wn^T)
__device__ float  g_sf[NN * 64];                // fp32 normalize(x @ Ws^T)
__device__ unsigned int g_cur[NN];              // per-node fill counters
__device__ unsigned long long g_ent[NN * CAPN]; // packed (key20 | w30 | j14)

__device__ __forceinline__ float wred(float v) {
#pragma unroll
    for (int o = 16; o; o >>= 1) v += __shfl_xor_sync(0xffffffffu, v, o);
    return v;
}

// ---------------------------------------------------------------------------
// 4 nodes per warp: both 64x64 GEMV projections + normalizations + x-hat.
// Weights packed as float4 (Ws_d, Ws_d+32, Wn_d, Wn_d+32) -> 1 LDS.128/k.
// Also zeroes g_cur (stream order guarantees visibility before k_edge).
// ---------------------------------------------------------------------------
__global__ __launch_bounds__(256) void k_transform(const float* __restrict__ x,
                                                   const float* __restrict__ Ws,
                                                   const float* __restrict__ Wn) {
    __shared__ float4 sW[64][32];   // [k][lane]
    for (int t = threadIdx.x; t < 4096; t += 256) {
        int d = t >> 6, k = t & 63;       // coalesced read Ws[d*64+k]
        float ws = Ws[t], wn = Wn[t];
        if (d < 32) { sW[k][d].x = ws; sW[k][d].z = wn; }
        else        { sW[k][d - 32].y = ws; sW[k][d - 32].w = wn; }
    }
    __syncthreads();
    int warp = threadIdx.x >> 5, lane = threadIdx.x & 31;
    int i0 = blockIdx.x * 32 + warp * 4;
    if (lane < 4) g_cur[i0 + lane] = 0u;

    float xa0[4], xa1[4];
#pragma unroll
    for (int n = 0; n < 4; n++) {
        xa0[n] = x[(i0 + n) * 64 + lane];
        xa1[n] = x[(i0 + n) * 64 + 32 + lane];
    }
    float s0[4] = {0, 0, 0, 0}, s1[4] = {0, 0, 0, 0};
    float a0[4] = {0, 0, 0, 0}, a1[4] = {0, 0, 0, 0};
#pragma unroll
    for (int k = 0; k < 32; k++) {
        float4 w = sW[k][lane];
#pragma unroll
        for (int n = 0; n < 4; n++) {
            float xk = __shfl_sync(0xffffffffu, xa0[n], k);
            s0[n] += xk * w.x; s1[n] += xk * w.y;
            a0[n] += xk * w.z; a1[n] += xk * w.w;
        }
    }
#pragma unroll
    for (int k = 0; k < 32; k++) {
        float4 w = sW[k + 32][lane];
#pragma unroll
        for (int n = 0; n < 4; n++) {
            float xk = __shfl_sync(0xffffffffu, xa1[n], k);
            s0[n] += xk * w.x; s1[n] += xk * w.y;
            a0[n] += xk * w.z; a1[n] += xk * w.w;
        }
    }
#pragma unroll
    for (int n = 0; n < 4; n++) {
        int i = i0 + n;
        float nx = wred(xa0[n] * xa0[n] + xa1[n] * xa1[n]);
        float ns = wred(s0[n] * s0[n] + s1[n] * s1[n]);
        float na = wred(a0[n] * a0[n] + a1[n] * a1[n]);
        float rx = 1.f / sqrtf(nx);
        float rs = 1.f / (sqrtf(ns) + EPSF);
        float ra = 1.f / (sqrtf(na) + EPSF);
        g_xnh[i * 64 + lane]      = __float2half_rn(xa0[n] * rx);
        g_xnh[i * 64 + 32 + lane] = __float2half_rn(xa1[n] * rx);
        g_anh[i * 64 + lane]      = __float2half_rn(a0[n] * ra);
        g_anh[i * 64 + 32 + lane] = __float2half_rn(a1[n] * ra);
        g_sf[i * 64 + lane]       = s0[n] * rs;
        g_sf[i * 64 + 32 + lane]  = s1[n] * rs;
    }
}

// ---------------------------------------------------------------------------
// One warp per edge: cosine weight from fp16 rows (128B each), then scatter
// BOTH directed incidences. key = k (pass-1 at (r,c)) or k+NE (pass-2 at
// (c,r)); max key == last .set() writer.
// ---------------------------------------------------------------------------
__global__ __launch_bounds__(256) void k_edge(const int* __restrict__ ei) {
    int warp = threadIdx.x >> 5, lane = threadIdx.x & 31;
    int k = blockIdx.x * 8 + warp;
    if (k >= NE) return;
    int r = ei[k], c = ei[NE + k];
    const __half2* pr = (const __half2*)(g_xnh + r * 64);
    const __half2* pc = (const __half2*)(g_xnh + c * 64);
    float2 fr = __half22float2(pr[lane]);
    float2 fc = __half22float2(pc[lane]);
    float d = wred(fr.x * fc.x + fr.y * fc.y);
    if (lane == 0) {
        float w = fminf(fmaxf((d + 1.f) * 0.5f, 0.1f), 0.9f);
        unsigned long long w30 = (unsigned long long)(__float_as_uint(w) >> 2);
        unsigned long long e1 = ((unsigned long long)(unsigned)k << 44) | (w30 << 14) | (unsigned)c;
        unsigned long long e2 = ((unsigned long long)(unsigned)(k + NE) << 44) | (w30 << 14) | (unsigned)r;
        unsigned int p = atomicAdd(&g_cur[r], 1u);
        if (p < CAPN) g_ent[r * CAPN + p] = e1;
        unsigned int q = atomicAdd(&g_cur[c], 1u);
        if (q < CAPN) g_ent[c * CAPN + q] = e2;
    }
}

// ---------------------------------------------------------------------------
// One warp per node: hash-table dedup (max packed value = max key wins),
// compact to (j, w) list, counted gather of fp16 rows (1 line each) + epilogue.
// ---------------------------------------------------------------------------
__global__ __launch_bounds__(256) void k_agg(const float* __restrict__ bias,
                                             float* __restrict__ out) {
    __shared__ unsigned long long tab[8][256];
    __shared__ int   sj[8][CAPN];
    __shared__ float sw[8][CAPN];
    int warp = threadIdx.x >> 5, lane = threadIdx.x & 31;

    float2 bv = ((const float2*)bias)[lane];     // dims 2l, 2l+1
    float nb = sqrtf(wred(bv.x * bv.x + bv.y * bv.y) + 1.0f);  // ||[bias,1]||
    float bp0 = bv.x / nb, bp1 = bv.y / nb;

    int i = blockIdx.x * 8 + warp;

#pragma unroll
    for (int t = lane; t < 256; t += 32) tab[warp][t] = 0ULL;
    __syncwarp();

    int deg = (int)min(g_cur[i], (unsigned)CAPN);
    for (int base = 0; base < deg; base += 32) {
        int e = base + lane;
        if (e < deg) {
            unsigned long long pe = g_ent[i * CAPN + e];
            unsigned int j = (unsigned int)(pe & 0x3FFFULL);
            unsigned int h = (j * 0x9E3779B1u) >> 24;
            for (;;) {
                unsigned long long cur = tab[warp][h];
                if (cur == 0ULL) {
                    unsigned long long old = atomicCAS(&tab[warp][h], 0ULL, pe);
                    if (old == 0ULL) break;
                    cur = old;
                }
                if ((unsigned int)(cur & 0x3FFFULL) == j) { atomicMax(&tab[warp][h], pe); break; }
                h = (h + 1) & 255;
            }
        }
    }
    __syncwarp();

    int cnt = 0, selfFlag = 0;
#pragma unroll
    for (int base = 0; base < 256; base += 32) {
        unsigned long long pe = tab[warp][base + lane];
        bool occ = pe != 0ULL;
        unsigned int j = (unsigned int)(pe & 0x3FFFULL);
        if (occ && j == (unsigned)i) selfFlag = 1;
        unsigned int mask = __ballot_sync(0xffffffffu, occ);
        int pos = cnt + __popc(mask & ((1u << lane) - 1u));
        if (occ) {
            sj[warp][pos] = (int)j;
            sw[warp][pos] = __uint_as_float(((unsigned int)(pe >> 14) & 0x3FFFFFFFu) << 2);
        }
        cnt += __popc(mask);
    }
    int hasSelf = (__ballot_sync(0xffffffffu, selfFlag) != 0u);
    __syncwarp();

    // counted gather: each lane owns dims (2l, 2l+1); one 128B line per row
    float acc0 = 0.f, acc1 = 0.f;
#pragma unroll 4
    for (int e = 0; e < cnt; e++) {
        int js = sj[warp][e];
        float wv = sw[warp][e];
        float2 f = __half22float2(((const __half2*)(g_anh + js * 64))[lane]);
        acc0 += wv * f.x;
        acc1 += wv * f.y;
    }
    if (!hasSelf) {  // eye diagonal survives only when no edge overwrote it
        float2 f = __half22float2(((const __half2*)(g_anh + i * 64))[lane]);
        acc0 += f.x;
        acc1 += f.y;
    }

    // epilogue: nf = normalize(acc); u = normalize(0.5 s + 0.5 nf);
    // m = normalize(0.9 u + 0.1 bp); final = m / (||m|| + eps)
    float na = wred(acc0 * acc0 + acc1 * acc1);
    float rn = 1.f / (sqrtf(na) + EPSF);
    float n0 = acc0 * rn, n1 = acc1 * rn;
    float2 sv = ((const float2*)(g_sf + i * 64))[lane];
    float u0 = 0.5f * (sv.x + n0), u1 = 0.5f * (sv.y + n1);
    float nu = wred(u0 * u0 + u1 * u1);
    float ru = 1.f / (sqrtf(nu) + EPSF);
    u0 *= ru; u1 *= ru;
    float m0 = 0.9f * u0 + 0.1f * bp0, m1 = 0.9f * u1 + 0.1f * bp1;
    float nm = wred(m0 * m0 + m1 * m1);
    float rm = 1.f / (sqrtf(nm) + EPSF);
    m0 *= rm; m1 *= rm;
    float nrm2 = sqrtf(nm) * rm;   // ~1
    float rf = 1.f / (nrm2 + EPSF);
    ((float2*)(out + i * 64))[lane] = make_float2(m0 * rf, m1 * rf);
}

extern "C" void kernel_launch(void* const* d_in, const int* in_sizes, int n_in,
                              void* d_out, int out_size) {
    const float* x  = (const float*)d_in[0];
    const int*   ei = (const int*)d_in[1];
    const float* Ws = (const float*)d_in[2];
    const float* Wn = (const float*)d_in[3];
    const float* b  = (const float*)d_in[4];
    float* out = (float*)d_out;

    k_transform<<<NN / 32, 256>>>(x, Ws, Wn);
    k_edge<<<NE / 8, 256>>>(ei);
    k_agg<<<NN / 8, 256>>>(b, out);
}

// round 4
// speedup vs baseline: 2.2307x; 1.2345x over previous
#include <cuda_runtime.h>
#include <cuda_fp16.h>

#define NN 12288
#define NE 393216
#define EPSF 1e-8f
#define CAPN 192          // fixed bucket capacity per node (deg ~ Poisson(64))
#define LCAP 16           // per-warp loser-list capacity (dups ~0.16/node)

// ---- scratch (static device globals; no allocation in kernel_launch) ----
__device__ __half g_xnh[NN * 64];               // fp16 x/||x|| (edge cosines)
__device__ __half g_anh[NN * 64];               // fp16 normalize(x @ Wn^T)
__device__ float  g_sf[NN * 64];                // fp32 normalize(x @ Ws^T)
__device__ unsigned int g_cur[NN];              // per-node fill counters
__device__ unsigned long long g_ent[NN * CAPN]; // packed (key20 | w30 | j14)

__device__ __forceinline__ float wred(float v) {
#pragma unroll
    for (int o = 16; o; o >>= 1) v += __shfl_xor_sync(0xffffffffu, v, o);
    return v;
}

// ---------------------------------------------------------------------------
// 4 nodes per warp. x staged transposed in shared -> inner loop is
// 8x LDS.128 per 64 FFMA (no shuffles). Also zeroes g_cur.
// ---------------------------------------------------------------------------
__global__ __launch_bounds__(256) void k_transform(const float* __restrict__ x,
                                                   const float* __restrict__ Ws,
                                                   const float* __restrict__ Wn) {
    __shared__ float4 sW[64][32];      // [k][lane] = (Ws_d, Ws_d+32, Wn_d, Wn_d+32)
    __shared__ float  sx[8][4][64];    // [warp][node][k]  (transposed x)
    for (int t = threadIdx.x; t < 4096; t += 256) {
        int d = t >> 6, k = t & 63;    // coalesced read W[d*64+k]
        float ws = Ws[t], wn = Wn[t];
        if (d < 32) { sW[k][d].x = ws; sW[k][d].z = wn; }
        else        { sW[k][d - 32].y = ws; sW[k][d - 32].w = wn; }
    }
    __syncthreads();
    int warp = threadIdx.x >> 5, lane = threadIdx.x & 31;
    int i0 = blockIdx.x * 32 + warp * 4;
    if (lane < 4) g_cur[i0 + lane] = 0u;

    float xa0[4], xa1[4];
#pragma unroll
    for (int n = 0; n < 4; n++) {
        xa0[n] = x[(i0 + n) * 64 + lane];
        xa1[n] = x[(i0 + n) * 64 + 32 + lane];
        sx[warp][n][lane]      = xa0[n];
        sx[warp][n][32 + lane] = xa1[n];
    }
    __syncwarp();

    float s0[4] = {0, 0, 0, 0}, s1[4] = {0, 0, 0, 0};
    float a0[4] = {0, 0, 0, 0}, a1[4] = {0, 0, 0, 0};
#pragma unroll
    for (int kb = 0; kb < 16; kb++) {
        float4 w0 = sW[kb * 4 + 0][lane];
        float4 w1 = sW[kb * 4 + 1][lane];
        float4 w2 = sW[kb * 4 + 2][lane];
        float4 w3 = sW[kb * 4 + 3][lane];
#pragma unroll
        for (int n = 0; n < 4; n++) {
            float4 xq = *(const float4*)&sx[warp][n][kb * 4];  // LDS.128 broadcast
            s0[n] += xq.x * w0.x + xq.y * w1.x + xq.z * w2.x + xq.w * w3.x;
            s1[n] += xq.x * w0.y + xq.y * w1.y + xq.z * w2.y + xq.w * w3.y;
            a0[n] += xq.x * w0.z + xq.y * w1.z + xq.z * w2.z + xq.w * w3.z;
            a1[n] += xq.x * w0.w + xq.y * w1.w + xq.z * w2.w + xq.w * w3.w;
        }
    }
#pragma unroll
    for (int n = 0; n < 4; n++) {
        int i = i0 + n;
        float nx = wred(xa0[n] * xa0[n] + xa1[n] * xa1[n]);
        float ns = wred(s0[n] * s0[n] + s1[n] * s1[n]);
        float na = wred(a0[n] * a0[n] + a1[n] * a1[n]);
        float rx = 1.f / sqrtf(nx);
        float rs = 1.f / (sqrtf(ns) + EPSF);
        float ra = 1.f / (sqrtf(na) + EPSF);
        g_xnh[i * 64 + lane]      = __float2half_rn(xa0[n] * rx);
        g_xnh[i * 64 + 32 + lane] = __float2half_rn(xa1[n] * rx);
        g_anh[i * 64 + lane]      = __float2half_rn(a0[n] * ra);
        g_anh[i * 64 + 32 + lane] = __float2half_rn(a1[n] * ra);
        g_sf[i * 64 + lane]       = s0[n] * rs;
        g_sf[i * 64 + 32 + lane]  = s1[n] * rs;
    }
}

// ---------------------------------------------------------------------------
// 4 edges per warp, 8 lanes per edge (2x LDG.128 per lane). Cosine weight,
// then scatter both directed incidences. key = k (pass-1 at (r,c)) or
// k+NE (pass-2 at (c,r)); max key == last .set() writer.
// ---------------------------------------------------------------------------
__global__ __launch_bounds__(256) void k_edge(const int* __restrict__ ei) {
    int warp = threadIdx.x >> 5, lane = threadIdx.x & 31;
    int sub = lane >> 3, l8 = lane & 7;
    int k = blockIdx.x * 32 + warp * 4 + sub;
    int r = __ldg(&ei[k]);
    int c = __ldg(&ei[NE + k]);
    uint4 ur = *(const uint4*)(g_xnh + r * 64 + l8 * 8);
    uint4 uc = *(const uint4*)(g_xnh + c * 64 + l8 * 8);
    const __half2* hr = (const __half2*)&ur;
    const __half2* hc = (const __half2*)&uc;
    float d = 0.f;
#pragma unroll
    for (int q = 0; q < 4; q++) {
        float2 a = __half22float2(hr[q]);
        float2 b = __half22float2(hc[q]);
        d += a.x * b.x + a.y * b.y;
    }
#pragma unroll
    for (int o = 4; o; o >>= 1) d += __shfl_xor_sync(0xffffffffu, d, o);
    if (l8 == 0) {
        float w = fminf(fmaxf((d + 1.f) * 0.5f, 0.1f), 0.9f);
        unsigned long long w30 = (unsigned long long)(__float_as_uint(w) >> 2);
        unsigned long long e1 = ((unsigned long long)(unsigned)k << 44) | (w30 << 14) | (unsigned)c;
        unsigned long long e2 = ((unsigned long long)(unsigned)(k + NE) << 44) | (w30 << 14) | (unsigned)r;
        unsigned int p = atomicAdd(&g_cur[r], 1u);
        if (p < CAPN) g_ent[r * CAPN + p] = e1;
        unsigned int q2 = atomicAdd(&g_cur[c], 1u);
        if (q2 < CAPN) g_ent[c * CAPN + q2] = e2;
    }
}

// ---------------------------------------------------------------------------
// One warp per node: gather ALL bucket entries unconditionally (max MLP);
// hash table only DETECTS duplicates; each atomicMax loser (= overwritten
// .set() writer) goes to a tiny list and is subtracted afterwards.
// ---------------------------------------------------------------------------
__global__ __launch_bounds__(256) void k_agg(const float* __restrict__ bias,
                                             float* __restrict__ out) {
    __shared__ unsigned long long tab[8][256];
    __shared__ int   lj[8][LCAP];
    __shared__ float lw[8][LCAP];
    __shared__ int   lcnt[8];
    int warp = threadIdx.x >> 5, lane = threadIdx.x & 31;

    float2 bv = ((const float2*)bias)[lane];                   // dims 2l, 2l+1
    float nb = sqrtf(wred(bv.x * bv.x + bv.y * bv.y) + 1.0f);  // ||[bias,1]||
    float bp0 = bv.x / nb, bp1 = bv.y / nb;

    int i = blockIdx.x * 8 + warp;
#pragma unroll
    for (int t = lane; t < 256; t += 32) tab[warp][t] = 0ULL;
    if (lane == 0) lcnt[warp] = 0;
    __syncwarp();

    int deg = (int)min(g_cur[i], (unsigned)CAPN);
    float acc0 = 0.f, acc1 = 0.f;
    int selfF = 0;

    for (int base = 0; base < deg; base += 32) {
        int e = base + lane;
        bool act = e < deg;
        unsigned long long pe = act ? g_ent[i * CAPN + e] : 0ULL;
        if (act) {
            unsigned int j = (unsigned int)(pe & 0x3FFFULL);
            if (j == (unsigned)i) selfF = 1;
            unsigned int h = (j * 0x9E3779B1u) >> 24;
            unsigned long long loser = 0ULL;
            for (;;) {
                unsigned long long cur = tab[warp][h];
                if (cur == 0ULL) {
                    unsigned long long old = atomicCAS(&tab[warp][h], 0ULL, pe);
                    if (old == 0ULL) break;
                    cur = old;
                }
                if ((unsigned int)(cur & 0x3FFFULL) == j) {
                    unsigned long long old = atomicMax(&tab[warp][h], pe);
                    loser = (old >= pe) ? pe : old;   // all-but-max lose once
                    break;
                }
                h = (h + 1) & 255;
            }
            if (loser != 0ULL) {
                int idx = atomicAdd(&lcnt[warp], 1);
                if (idx < LCAP) {
                    lj[warp][idx] = (int)(loser & 0x3FFFULL);
                    lw[warp][idx] = __uint_as_float(((unsigned int)(loser >> 14) & 0x3FFFFFFFu) << 2);
                }
            }
        }
        int m = min(deg - base, 32);
#pragma unroll 4
        for (int t = 0; t < m; t++) {
            unsigned long long ps = __shfl_sync(0xffffffffu, pe, t);
            int js = (int)(ps & 0x3FFFULL);
            float wv = __uint_as_float(((unsigned int)(ps >> 14) & 0x3FFFFFFFu) << 2);
            float2 f = __half22float2(((const __half2*)(g_anh + js * 64))[lane]);
            acc0 += wv * f.x;
            acc1 += wv * f.y;
        }
    }
    int hasSelf = (__ballot_sync(0xffffffffu, selfF) != 0u);
    __syncwarp();

    // subtract the losers (rare)
    int lc = min(lcnt[warp], LCAP);
    for (int t = 0; t < lc; t++) {
        int js = lj[warp][t];
        float wv = lw[warp][t];
        float2 f = __half22float2(((const __half2*)(g_anh + js * 64))[lane]);
        acc0 -= wv * f.x;
        acc1 -= wv * f.y;
    }
    if (!hasSelf) {  // eye diagonal survives only when no edge overwrote it
        float2 f = __half22float2(((const __half2*)(g_anh + i * 64))[lane]);
        acc0 += f.x;
        acc1 += f.y;
    }

    // epilogue: nf = normalize(acc); u = normalize(0.5 s + 0.5 nf);
    // m = normalize(0.9 u + 0.1 bp); final = m / (||m|| + eps)
    float na = wred(acc0 * acc0 + acc1 * acc1);
    float rn = 1.f / (sqrtf(na) + EPSF);
    float n0 = acc0 * rn, n1 = acc1 * rn;
    float2 sv = ((const float2*)(g_sf + i * 64))[lane];
    float u0 = 0.5f * (sv.x + n0), u1 = 0.5f * (sv.y + n1);
    float nu = wred(u0 * u0 + u1 * u1);
    float ru = 1.f / (sqrtf(nu) + EPSF);
    u0 *= ru; u1 *= ru;
    float m0 = 0.9f * u0 + 0.1f * bp0, m1 = 0.9f * u1 + 0.1f * bp1;
    float nm = wred(m0 * m0 + m1 * m1);
    float rm = 1.f / (sqrtf(nm) + EPSF);
    m0 *= rm; m1 *= rm;
    float nrm2 = sqrtf(nm) * rm;   // ~1
    float rf = 1.f / (nrm2 + EPSF);
    ((float2*)(out + i * 64))[lane] = make_float2(m0 * rf, m1 * rf);
}

extern "C" void kernel_launch(void* const* d_in, const int* in_sizes, int n_in,
                              void* d_out, int out_size) {
    const float* x  = (const float*)d_in[0];
    const int*   ei = (const int*)d_in[1];
    const float* Ws = (const float*)d_in[2];
    const float* Wn = (const float*)d_in[3];
    const float* b  = (const float*)d_in[4];
    float* out = (float*)d_out;

    k_transform<<<NN / 32, 256>>>(x, Ws, Wn);
    k_edge<<<NE / 32, 256>>>(ei);
    k_agg<<<NN / 8, 256>>>(b, out);
}

// round 5
// speedup vs baseline: 3.2999x; 1.4793x over previous
#include <cuda_runtime.h>
#include <cuda_fp16.h>

#define NN 12288
#define NE 393216
#define EPSF 1e-8f
#define CAPN 192          // fixed bucket capacity per node (deg ~ Poisson(64))
#define LCAP 16           // per-warp conflict-list capacity (dups ~0.16/node)

// ---- scratch (static device globals; no allocation in kernel_launch) ----
__device__ float4 g_wp[64 * 32];                // packed (WsT, WsT+32, WnT, WnT+32)
__device__ __half g_xnh[NN * 64];               // fp16 x/||x|| (edge cosines)
__device__ __half g_anh[NN * 64];               // fp16 normalize(x @ Wn^T)
__device__ float  g_sf[NN * 64];                // fp32 normalize(x @ Ws^T)
__device__ unsigned int g_cur[NN];              // per-node fill counters
__device__ unsigned long long g_ent[NN * CAPN]; // packed (key20 | w30 | j14)

__device__ __forceinline__ float wred(float v) {
#pragma unroll
    for (int o = 16; o; o >>= 1) v += __shfl_xor_sync(0xffffffffu, v, o);
    return v;
}
__device__ __forceinline__ float entw(unsigned long long pe) {
    return __uint_as_float(((unsigned int)(pe >> 14) & 0x3FFFFFFFu) << 2);
}

// ---------------------------------------------------------------------------
// Prep: repack W into interleaved float4 (L1-resident afterwards) + zero g_cur.
// ---------------------------------------------------------------------------
__global__ void k_prep(const float* __restrict__ Ws, const float* __restrict__ Wn) {
    int t = blockIdx.x * blockDim.x + threadIdx.x;
    if (t < NN) g_cur[t] = 0u;
    if (t < 2048) {
        int k = t >> 5, l = t & 31;
        g_wp[k * 32 + l] = make_float4(Ws[l * 64 + k], Ws[(l + 32) * 64 + k],
                                       Wn[l * 64 + k], Wn[(l + 32) * 64 + k]);
    }
}

// ---------------------------------------------------------------------------
// 2 nodes per warp, 128-thread blocks (grid 1536 -> high occupancy).
// W read via coalesced LDG.128 (L1-hit after first touch); x broadcast from
// a tiny per-warp smem buffer. No __syncthreads anywhere.
// ---------------------------------------------------------------------------
__global__ __launch_bounds__(128) void k_transform(const float* __restrict__ x) {
    __shared__ float sx[4][2][64];     // [warp][node][k]
    int warp = threadIdx.x >> 5, lane = threadIdx.x & 31;
    int i0 = blockIdx.x * 8 + warp * 2;

    float xa0[2], xa1[2];
#pragma unroll
    for (int n = 0; n < 2; n++) {
        xa0[n] = x[(i0 + n) * 64 + lane];
        xa1[n] = x[(i0 + n) * 64 + 32 + lane];
        sx[warp][n][lane]      = xa0[n];
        sx[warp][n][32 + lane] = xa1[n];
    }
    __syncwarp();

    float s0[2] = {0, 0}, s1[2] = {0, 0}, a0[2] = {0, 0}, a1[2] = {0, 0};
#pragma unroll
    for (int kb = 0; kb < 16; kb++) {
        float4 w0 = __ldg(&g_wp[(kb * 4 + 0) * 32 + lane]);
        float4 w1 = __ldg(&g_wp[(kb * 4 + 1) * 32 + lane]);
        float4 w2 = __ldg(&g_wp[(kb * 4 + 2) * 32 + lane]);
        float4 w3 = __ldg(&g_wp[(kb * 4 + 3) * 32 + lane]);
#pragma unroll
        for (int n = 0; n < 2; n++) {
            float4 xq = *(const float4*)&sx[warp][n][kb * 4];  // LDS.128 broadcast
            s0[n] += xq.x * w0.x + xq.y * w1.x + xq.z * w2.x + xq.w * w3.x;
            s1[n] += xq.x * w0.y + xq.y * w1.y + xq.z * w2.y + xq.w * w3.y;
            a0[n] += xq.x * w0.z + xq.y * w1.z + xq.z * w2.z + xq.w * w3.z;
            a1[n] += xq.x * w0.w + xq.y * w1.w + xq.z * w2.w + xq.w * w3.w;
        }
    }
#pragma unroll
    for (int n = 0; n < 2; n++) {
        int i = i0 + n;
        float nx = wred(xa0[n] * xa0[n] + xa1[n] * xa1[n]);
        float ns = wred(s0[n] * s0[n] + s1[n] * s1[n]);
        float na = wred(a0[n] * a0[n] + a1[n] * a1[n]);
        float rx = 1.f / sqrtf(nx);
        float rs = 1.f / (sqrtf(ns) + EPSF);
        float ra = 1.f / (sqrtf(na) + EPSF);
        g_xnh[i * 64 + lane]      = __float2half_rn(xa0[n] * rx);
        g_xnh[i * 64 + 32 + lane] = __float2half_rn(xa1[n] * rx);
        g_anh[i * 64 + lane]      = __float2half_rn(a0[n] * ra);
        g_anh[i * 64 + 32 + lane] = __float2half_rn(a1[n] * ra);
        g_sf[i * 64 + lane]       = s0[n] * rs;
        g_sf[i * 64 + 32 + lane]  = s1[n] * rs;
    }
}

// ---------------------------------------------------------------------------
// 4 edges per warp, 8 lanes per edge. Cosine weight, then scatter both
// directed incidences. key = k (pass-1 at (r,c)) or k+NE (pass-2 at (c,r));
// max key == last .set() writer.
// ---------------------------------------------------------------------------
__global__ __launch_bounds__(256) void k_edge(const int* __restrict__ ei) {
    int warp = threadIdx.x >> 5, lane = threadIdx.x & 31;
    int sub = lane >> 3, l8 = lane & 7;
    int k = blockIdx.x * 32 + warp * 4 + sub;
    int r = __ldg(&ei[k]);
    int c = __ldg(&ei[NE + k]);
    uint4 ur = *(const uint4*)(g_xnh + r * 64 + l8 * 8);
    uint4 uc = *(const uint4*)(g_xnh + c * 64 + l8 * 8);
    const __half2* hr = (const __half2*)&ur;
    const __half2* hc = (const __half2*)&uc;
    float d = 0.f;
#pragma unroll
    for (int q = 0; q < 4; q++) {
        float2 a = __half22float2(hr[q]);
        float2 b = __half22float2(hc[q]);
        d += a.x * b.x + a.y * b.y;
    }
#pragma unroll
    for (int o = 4; o; o >>= 1) d += __shfl_xor_sync(0xffffffffu, d, o);
    if (l8 == 0) {
        float w = fminf(fmaxf((d + 1.f) * 0.5f, 0.1f), 0.9f);
        unsigned long long w30 = (unsigned long long)(__float_as_uint(w) >> 2);
        unsigned long long e1 = ((unsigned long long)(unsigned)k << 44) | (w30 << 14) | (unsigned)c;
        unsigned long long e2 = ((unsigned long long)(unsigned)(k + NE) << 44) | (w30 << 14) | (unsigned)r;
        unsigned int p = atomicAdd(&g_cur[r], 1u);
        if (p < CAPN) g_ent[r * CAPN + p] = e1;
        unsigned int q2 = atomicAdd(&g_cur[c], 1u);
        if (q2 < CAPN) g_ent[c * CAPN + q2] = e2;
    }
}

// ---------------------------------------------------------------------------
// One warp per node: gather ALL entries unconditionally (max MLP). A presence
// BITMAP (1 atomicOr/entry) detects duplicate j's; rare conflicts get an exact
// rescan that keeps only the max-key writer (JAX .set semantics).
// ---------------------------------------------------------------------------
__global__ __launch_bounds__(256) void k_agg(const float* __restrict__ bias,
                                             float* __restrict__ out) {
    __shared__ unsigned int bm[8][384];   // 12288-bit presence map per warp
    __shared__ int cj[8][LCAP];
    __shared__ int ccnt[8];
    int warp = threadIdx.x >> 5, lane = threadIdx.x & 31;

    float2 bv = ((const float2*)bias)[lane];                   // dims 2l, 2l+1
    float nb = sqrtf(wred(bv.x * bv.x + bv.y * bv.y) + 1.0f);  // ||[bias,1]||
    float bp0 = bv.x / nb, bp1 = bv.y / nb;

    int i = blockIdx.x * 8 + warp;
#pragma unroll
    for (int t = lane; t < 384; t += 32) bm[warp][t] = 0u;
    if (lane == 0) ccnt[warp] = 0;
    __syncwarp();

    int deg = (int)min(g_cur[i], (unsigned)CAPN);
    float acc0 = 0.f, acc1 = 0.f;
    int selfF = 0;

    for (int base = 0; base < deg; base += 32) {
        int e = base + lane;
        bool act = e < deg;
        unsigned long long pe = act ? g_ent[i * CAPN + e] : 0ULL;
        if (act) {
            unsigned int j = (unsigned int)(pe & 0x3FFFULL);
            if (j == (unsigned)i) selfF = 1;
            unsigned int old = atomicOr(&bm[warp][j >> 5], 1u << (j & 31));
            if (old & (1u << (j & 31))) {          // duplicate j -> conflict
                int idx = atomicAdd(&ccnt[warp], 1);
                if (idx < LCAP) cj[warp][idx] = (int)j;
            }
        }
        int m = min(deg - base, 32);
#pragma unroll 4
        for (int t = 0; t < m; t++) {
            unsigned long long ps = __shfl_sync(0xffffffffu, pe, t);
            int js = (int)(ps & 0x3FFFULL);
            float wv = entw(ps);
            float2 f = __half22float2(((const __half2*)(g_anh + js * 64))[lane]);
            acc0 += wv * f.x;
            acc1 += wv * f.y;
        }
    }
    int hasSelf = (__ballot_sync(0xffffffffu, selfF) != 0u);
    __syncwarp();

    // exact fixup for conflicted j's (rare): keep only the max-key entry
    int cc = min(ccnt[warp], LCAP);
    for (int t = 0; t < cc; t++) {
        int j = cj[warp][t];
        bool seen = false;                 // same j may be pushed multiple times
        for (int u = 0; u < t; u++) if (cj[warp][u] == j) { seen = true; break; }
        if (seen) continue;
        float wsum = 0.f;
        unsigned long long best = 0ULL;
        for (int base = 0; base < deg; base += 32) {
            int e = base + lane;
            unsigned long long pe = (e < deg) ? g_ent[i * CAPN + e] : 0ULL;
            if (pe && (int)(pe & 0x3FFFULL) == j) {
                wsum += entw(pe);
                best = max(best, pe);
            }
        }
        wsum = wred(wsum);
#pragma unroll
        for (int o = 16; o; o >>= 1) {
            unsigned long long v = __shfl_xor_sync(0xffffffffu, best, o);
            best = max(best, v);
        }
        float corr = wsum - entw(best);    // subtract all losers
        float2 f = __half22float2(((const __half2*)(g_anh + j * 64))[lane]);
        acc0 -= corr * f.x;
        acc1 -= corr * f.y;
    }
    if (!hasSelf) {  // eye diagonal survives only when no edge overwrote it
        float2 f = __half22float2(((const __half2*)(g_anh + i * 64))[lane]);
        acc0 += f.x;
        acc1 += f.y;
    }

    // epilogue: nf = normalize(acc); u = normalize(0.5 s + 0.5 nf);
    // m = normalize(0.9 u + 0.1 bp); final = m / (||m|| + eps)
    float na = wred(acc0 * acc0 + acc1 * acc1);
    float rn = 1.f / (sqrtf(na) + EPSF);
    float n0 = acc0 * rn, n1 = acc1 * rn;
    float2 sv = ((const float2*)(g_sf + i * 64))[lane];
    float u0 = 0.5f * (sv.x + n0), u1 = 0.5f * (sv.y + n1);
    float nu = wred(u0 * u0 + u1 * u1);
    float ru = 1.f / (sqrtf(nu) + EPSF);
    u0 *= ru; u1 *= ru;
    float m0 = 0.9f * u0 + 0.1f * bp0, m1 = 0.9f * u1 + 0.1f * bp1;
    float nm = wred(m0 * m0 + m1 * m1);
    float rm = 1.f / (sqrtf(nm) + EPSF);
    m0 *= rm; m1 *= rm;
    float nrm2 = sqrtf(nm) * rm;   // ~1
    float rf = 1.f / (nrm2 + EPSF);
    ((float2*)(out + i * 64))[lane] = make_float2(m0 * rf, m1 * rf);
}

extern "C" void kernel_launch(void* const* d_in, const int* in_sizes, int n_in,
                              void* d_out, int out_size) {
    const float* x  = (const float*)d_in[0];
    const int*   ei = (const int*)d_in[1];
    const float* Ws = (const float*)d_in[2];
    const float* Wn = (const float*)d_in[3];
    const float* b  = (const float*)d_in[4];
    float* out = (float*)d_out;

    k_prep<<<NN / 256, 256>>>(Ws, Wn);
    k_transform<<<NN / 8, 128>>>(x);
    k_edge<<<NE / 32, 256>>>(ei);
    k_agg<<<NN / 8, 256>>>(b, out);
}

// round 6
// speedup vs baseline: 3.5905x; 1.0881x over previous
#include <cuda_runtime.h>
#include <cuda_fp16.h>

#define NN 12288
#define NE 393216
#define EPSF 1e-8f
#define CAPN 192          // fixed bucket capacity per node (deg ~ Poisson(64))
#define LCAP 16           // per-warp conflict-list capacity (dups ~0.16/node)

// ---- scratch (static device globals; no allocation in kernel_launch) ----
__device__ float4 g_wp[64 * 32];                // packed (WsT, WsT+32, WnT, WnT+32)
__device__ __half g_xnh[NN * 64];               // fp16 x/||x|| (edge cosines)
__device__ __half g_anh[NN * 64];               // fp16 normalize(x @ Wn^T)
__device__ float  g_sf[NN * 64];                // fp32 normalize(x @ Ws^T)
__device__ unsigned int g_cur[NN];              // per-node fill counters
__device__ unsigned long long g_ent[NN * CAPN]; // packed (key20 | w30 | j14)
__device__ unsigned int g_pay[NN * CAPN];       // packed (fp16(w)<<16 | j14)

__device__ __forceinline__ float wred(float v) {
#pragma unroll
    for (int o = 16; o; o >>= 1) v += __shfl_xor_sync(0xffffffffu, v, o);
    return v;
}
__device__ __forceinline__ float entw(unsigned long long pe) {
    return __uint_as_float(((unsigned int)(pe >> 14) & 0x3FFFFFFFu) << 2);
}
__device__ __forceinline__ float payw(unsigned int p) {
    return __half2float(__ushort_as_half((unsigned short)(p >> 16)));
}

// ---------------------------------------------------------------------------
// Prep: repack W into interleaved float4 (L1-resident afterwards) + zero g_cur.
// ---------------------------------------------------------------------------
__global__ void k_prep(const float* __restrict__ Ws, const float* __restrict__ Wn) {
    int t = blockIdx.x * blockDim.x + threadIdx.x;
    if (t < NN) g_cur[t] = 0u;
    if (t < 2048) {
        int k = t >> 5, l = t & 31;
        g_wp[k * 32 + l] = make_float4(Ws[l * 64 + k], Ws[(l + 32) * 64 + k],
                                       Wn[l * 64 + k], Wn[(l + 32) * 64 + k]);
    }
}

// ---------------------------------------------------------------------------
// 2 nodes per warp, 128-thread blocks. W via coalesced LDG.128 (L1-hit),
// x broadcast from tiny per-warp smem. No __syncthreads.
// ---------------------------------------------------------------------------
__global__ __launch_bounds__(128) void k_transform(const float* __restrict__ x) {
    __shared__ float sx[4][2][64];     // [warp][node][k]
    int warp = threadIdx.x >> 5, lane = threadIdx.x & 31;
    int i0 = blockIdx.x * 8 + warp * 2;

    float xa0[2], xa1[2];
#pragma unroll
    for (int n = 0; n < 2; n++) {
        xa0[n] = x[(i0 + n) * 64 + lane];
        xa1[n] = x[(i0 + n) * 64 + 32 + lane];
        sx[warp][n][lane]      = xa0[n];
        sx[warp][n][32 + lane] = xa1[n];
    }
    __syncwarp();

    float s0[2] = {0, 0}, s1[2] = {0, 0}, a0[2] = {0, 0}, a1[2] = {0, 0};
#pragma unroll
    for (int kb = 0; kb < 16; kb++) {
        float4 w0 = __ldg(&g_wp[(kb * 4 + 0) * 32 + lane]);
        float4 w1 = __ldg(&g_wp[(kb * 4 + 1) * 32 + lane]);
        float4 w2 = __ldg(&g_wp[(kb * 4 + 2) * 32 + lane]);
        float4 w3 = __ldg(&g_wp[(kb * 4 + 3) * 32 + lane]);
#pragma unroll
        for (int n = 0; n < 2; n++) {
            float4 xq = *(const float4*)&sx[warp][n][kb * 4];  // LDS.128 broadcast
            s0[n] += xq.x * w0.x + xq.y * w1.x + xq.z * w2.x + xq.w * w3.x;
            s1[n] += xq.x * w0.y + xq.y * w1.y + xq.z * w2.y + xq.w * w3.y;
            a0[n] += xq.x * w0.z + xq.y * w1.z + xq.z * w2.z + xq.w * w3.z;
            a1[n] += xq.x * w0.w + xq.y * w1.w + xq.z * w2.w + xq.w * w3.w;
        }
    }
#pragma unroll
    for (int n = 0; n < 2; n++) {
        int i = i0 + n;
        float nx = wred(xa0[n] * xa0[n] + xa1[n] * xa1[n]);
        float ns = wred(s0[n] * s0[n] + s1[n] * s1[n]);
        float na = wred(a0[n] * a0[n] + a1[n] * a1[n]);
        float rx = 1.f / sqrtf(nx);
        float rs = 1.f / (sqrtf(ns) + EPSF);
        float ra = 1.f / (sqrtf(na) + EPSF);
        g_xnh[i * 64 + lane]      = __float2half_rn(xa0[n] * rx);
        g_xnh[i * 64 + 32 + lane] = __float2half_rn(xa1[n] * rx);
        g_anh[i * 64 + lane]      = __float2half_rn(a0[n] * ra);
        g_anh[i * 64 + 32 + lane] = __float2half_rn(a1[n] * ra);
        g_sf[i * 64 + lane]       = s0[n] * rs;
        g_sf[i * 64 + 32 + lane]  = s1[n] * rs;
    }
}

// ---------------------------------------------------------------------------
// 4 edges per warp, 8 lanes per edge. Cosine weight, then scatter both
// directed incidences (u64 key entry + u32 gather payload).
// key = k (pass-1 at (r,c)) or k+NE (pass-2 at (c,r)); max key = last writer.
// ---------------------------------------------------------------------------
__global__ __launch_bounds__(256) void k_edge(const int* __restrict__ ei) {
    int warp = threadIdx.x >> 5, lane = threadIdx.x & 31;
    int sub = lane >> 3, l8 = lane & 7;
    int k = blockIdx.x * 32 + warp * 4 + sub;
    int r = __ldg(&ei[k]);
    int c = __ldg(&ei[NE + k]);
    uint4 ur = *(const uint4*)(g_xnh + r * 64 + l8 * 8);
    uint4 uc = *(const uint4*)(g_xnh + c * 64 + l8 * 8);
    const __half2* hr = (const __half2*)&ur;
    const __half2* hc = (const __half2*)&uc;
    float d = 0.f;
#pragma unroll
    for (int q = 0; q < 4; q++) {
        float2 a = __half22float2(hr[q]);
        float2 b = __half22float2(hc[q]);
        d += a.x * b.x + a.y * b.y;
    }
#pragma unroll
    for (int o = 4; o; o >>= 1) d += __shfl_xor_sync(0xffffffffu, d, o);
    if (l8 == 0) {
        float w = fminf(fmaxf((d + 1.f) * 0.5f, 0.1f), 0.9f);
        unsigned long long w30 = (unsigned long long)(__float_as_uint(w) >> 2);
        unsigned int hw = (unsigned int)__half_as_ushort(__float2half_rn(w));
        unsigned long long e1 = ((unsigned long long)(unsigned)k << 44) | (w30 << 14) | (unsigned)c;
        unsigned long long e2 = ((unsigned long long)(unsigned)(k + NE) << 44) | (w30 << 14) | (unsigned)r;
        unsigned int p = atomicAdd(&g_cur[r], 1u);
        if (p < CAPN) { g_ent[r * CAPN + p] = e1; g_pay[r * CAPN + p] = (hw << 16) | (unsigned)c; }
        unsigned int q2 = atomicAdd(&g_cur[c], 1u);
        if (q2 < CAPN) { g_ent[c * CAPN + q2] = e2; g_pay[c * CAPN + q2] = (hw << 16) | (unsigned)r; }
    }
}

// ---------------------------------------------------------------------------
// One warp per node. Phase A: coalesced payload load -> smem staging + bitmap
// dup-detect (1 atomicOr/entry). Phase B: 4 entries/iteration, 8 lanes/entry,
// LDG.128 per row; group sums combined via shfl_xor(8,16). Self-add and exact
// max-key fixup (JAX .set semantics) applied after reduction.
// ---------------------------------------------------------------------------
__global__ __launch_bounds__(256) void k_agg(const float* __restrict__ bias,
                                             float* __restrict__ out) {
    __shared__ unsigned int bm[8][384];       // 12288-bit presence map per warp
    __shared__ unsigned int spay[8][CAPN + 4];
    __shared__ int cj[8][LCAP];
    __shared__ int ccnt[8];
    int warp = threadIdx.x >> 5, lane = threadIdx.x & 31;
    int sub = lane >> 3, l8 = lane & 7;
    int i = blockIdx.x * 8 + warp;

#pragma unroll
    for (int t = lane; t < 384; t += 32) bm[warp][t] = 0u;
    if (lane == 0) ccnt[warp] = 0;
    __syncwarp();

    int deg = (int)min(g_cur[i], (unsigned)CAPN);
    int selfF = 0;

    // Phase A: stage payloads + duplicate detection
    for (int base = 0; base < deg; base += 32) {
        int e = base + lane;
        if (e < deg) {
            unsigned int p = __ldg(&g_pay[i * CAPN + e]);
            spay[warp][e] = p;
            unsigned int j = p & 0x3FFFu;
            if (j == (unsigned)i) selfF = 1;
            unsigned int old = atomicOr(&bm[warp][j >> 5], 1u << (j & 31));
            if (old & (1u << (j & 31))) {
                int idx = atomicAdd(&ccnt[warp], 1);
                if (idx < LCAP) cj[warp][idx] = (int)j;
            }
        }
    }
    if (lane < 4) spay[warp][deg + lane] = 0u;   // zero-weight padding
    int hasSelf = (__ballot_sync(0xffffffffu, selfF) != 0u);
    __syncwarp();

    // Phase B: gather, 4 entries per iteration; lane owns dims l8*8 .. l8*8+7
    float acc[8] = {0, 0, 0, 0, 0, 0, 0, 0};
    for (int t = 0; t < deg; t += 4) {
        unsigned int p = spay[warp][t + sub];
        int js = (int)(p & 0x3FFFu);
        float wv = payw(p);
        uint4 u = *(const uint4*)(g_anh + js * 64 + l8 * 8);
        const __half2* h = (const __half2*)&u;
#pragma unroll
        for (int q = 0; q < 4; q++) {
            float2 f = __half22float2(h[q]);
            acc[2 * q]     += wv * f.x;
            acc[2 * q + 1] += wv * f.y;
        }
    }
    // combine the 4 sub-groups (all groups end with identical full sums)
#pragma unroll
    for (int d = 0; d < 8; d++) {
        acc[d] += __shfl_xor_sync(0xffffffffu, acc[d], 8);
        acc[d] += __shfl_xor_sync(0xffffffffu, acc[d], 16);
    }

    // exact fixup for conflicted j's (rare): keep only the max-key writer
    int cc = min(ccnt[warp], LCAP);
    for (int t = 0; t < cc; t++) {
        int j = cj[warp][t];
        bool seen = false;
        for (int u2 = 0; u2 < t; u2++) if (cj[warp][u2] == j) { seen = true; break; }
        if (seen) continue;
        float wsum = 0.f;
        unsigned long long best = 0ULL;
        for (int base = 0; base < deg; base += 32) {
            int e = base + lane;
            unsigned long long pe = (e < deg) ? g_ent[i * CAPN + e] : 0ULL;
            if (pe && (int)(pe & 0x3FFFULL) == j) {
                wsum += __half2float(__float2half_rn(entw(pe)));  // match gather encoding
                best = max(best, pe);
            }
        }
        wsum = wred(wsum);
#pragma unroll
        for (int o = 16; o; o >>= 1) {
            unsigned long long v = __shfl_xor_sync(0xffffffffu, best, o);
            best = max(best, v);
        }
        float corr = wsum - __half2float(__float2half_rn(entw(best)));
        uint4 u = *(const uint4*)(g_anh + j * 64 + l8 * 8);
        const __half2* h = (const __half2*)&u;
#pragma unroll
        for (int q = 0; q < 4; q++) {
            float2 f = __half22float2(h[q]);
            acc[2 * q]     -= corr * f.x;
            acc[2 * q + 1] -= corr * f.y;
        }
    }
    if (!hasSelf) {   // eye diagonal survives only when no edge overwrote it
        uint4 u = *(const uint4*)(g_anh + i * 64 + l8 * 8);
        const __half2* h = (const __half2*)&u;
#pragma unroll
        for (int q = 0; q < 4; q++) {
            float2 f = __half22float2(h[q]);
            acc[2 * q]     += f.x;
            acc[2 * q + 1] += f.y;
        }
    }

    // epilogue (dims replicated 4x across sub-groups: norms = wred(.)/4)
    float bp[8];
    {
        float4 b0 = *(const float4*)(bias + l8 * 8);
        float4 b1 = *(const float4*)(bias + l8 * 8 + 4);
        bp[0] = b0.x; bp[1] = b0.y; bp[2] = b0.z; bp[3] = b0.w;
        bp[4] = b1.x; bp[5] = b1.y; bp[6] = b1.z; bp[7] = b1.w;
        float sb = 0.f;
#pragma unroll
        for (int d = 0; d < 8; d++) sb += bp[d] * bp[d];
        float nb = sqrtf(wred(sb) * 0.25f + 1.0f);   // ||[bias,1]||
#pragma unroll
        for (int d = 0; d < 8; d++) bp[d] /= nb;
    }
    float sq = 0.f;
#pragma unroll
    for (int d = 0; d < 8; d++) sq += acc[d] * acc[d];
    float na = wred(sq) * 0.25f;
    float rn = 1.f / (sqrtf(na) + EPSF);

    float sv[8];
    {
        float4 s0 = *(const float4*)(g_sf + i * 64 + l8 * 8);
        float4 s1 = *(const float4*)(g_sf + i * 64 + l8 * 8 + 4);
        sv[0] = s0.x; sv[1] = s0.y; sv[2] = s0.z; sv[3] = s0.w;
        sv[4] = s1.x; sv[5] = s1.y; sv[6] = s1.z; sv[7] = s1.w;
    }
    float u8[8]; float squ = 0.f;
#pragma unroll
    for (int d = 0; d < 8; d++) { u8[d] = 0.5f * (sv[d] + acc[d] * rn); squ += u8[d] * u8[d]; }
    float nu = wred(squ) * 0.25f;
    float ru = 1.f / (sqrtf(nu) + EPSF);
    float m8[8]; float sqm = 0.f;
#pragma unroll
    for (int d = 0; d < 8; d++) { m8[d] = 0.9f * u8[d] * ru + 0.1f * bp[d]; sqm += m8[d] * m8[d]; }
    float nm = wred(sqm) * 0.25f;
    float rm = 1.f / (sqrtf(nm) + EPSF);
    float nrm2 = sqrtf(nm) * rm;   // ~1
    float rf = rm / (nrm2 + EPSF);
    if (sub == 0) {
        float4 o0 = make_float4(m8[0] * rf, m8[1] * rf, m8[2] * rf, m8[3] * rf);
        float4 o1 = make_float4(m8[4] * rf, m8[5] * rf, m8[6] * rf, m8[7] * rf);
        *(float4*)(out + i * 64 + l8 * 8)     = o0;
        *(float4*)(out + i * 64 + l8 * 8 + 4) = o1;
    }
}

extern "C" void kernel_launch(void* const* d_in, const int* in_sizes, int n_in,
                              void* d_out, int out_size) {
    const float* x  = (const float*)d_in[0];
    const int*   ei = (const int*)d_in[1];
    const float* Ws = (const float*)d_in[2];
    const float* Wn = (const float*)d_in[3];
    const float* b  = (const float*)d_in[4];
    float* out = (float*)d_out;

    k_prep<<<NN / 256, 256>>>(Ws, Wn);
    k_transform<<<NN / 8, 128>>>(x);
    k_edge<<<NE / 32, 256>>>(ei);
    k_agg<<<NN / 8, 256>>>(b, out);
}